// round 8
// baseline (speedup 1.0000x reference)
#include <cuda_runtime.h>
#include <cuda_fp16.h>
#include <cstdint>

// GeometricEdgeConv v5: per-batch pipelined prepass+gather (forked streams).
//  prepass(b): y[b] fp16 = x[b] @ [Ws | We_feat]  (HMMA), + aug[p]=(pos,|pos|^2)
//  gather(b):  out[p] = leaky( y_self[p] + mean_k y_edge[idx] + pos-GEMV )
// gather(b) depends only on prepass(b) -> cross-stream event pipeline hides
// the GEMM under earlier batches' gathers.

namespace {

constexpr int Nn = 16384;

constexpr int KH = 136;                    // 128 k + 8 pad halves
constexpr int RB = KH * 2;                 // 272 B row (LDSM conflict-free)
constexpr int SM_B2 = 0;                   // W2^T fp16: 256 rows
constexpr int SM_A2 = 256 * RB;            // x tile fp16
constexpr int SM_Y  = SM_A2 + 128 * RB;    // y stage: 128 x 264 halves
constexpr int YSTR  = 264;
constexpr int SM2_TOTAL = SM_Y + 128 * YSTR * 2;   // 172032

__device__ __half g_y[(size_t)131072 * 256];       // 64 MB scratch
__device__ float  g_aug[(size_t)131072 * 4];       // 2 MB: pos + |pos|^2

__device__ __forceinline__ uint32_t smem_u32(const void* p) {
    uint32_t a;
    asm("{ .reg .u64 t; cvta.to.shared.u64 t, %1; cvt.u32.u64 %0, t; }" : "=r"(a) : "l"(p));
    return a;
}
__device__ __forceinline__ uint32_t cvt2h(float a, float b) {  // lo=a, hi=b
    uint32_t r;
    asm("cvt.rn.f16x2.f32 %0, %1, %2;" : "=r"(r) : "f"(b), "f"(a));
    return r;
}
__device__ __forceinline__ void sts32(uint32_t addr, uint32_t v) {
    asm volatile("st.shared.b32 [%0], %1;" :: "r"(addr), "r"(v) : "memory");
}
__device__ __forceinline__ void sts64(uint32_t addr, uint32_t a, uint32_t b) {
    asm volatile("st.shared.v2.b32 [%0], {%1,%2};" :: "r"(addr), "r"(a), "r"(b) : "memory");
}
__device__ __forceinline__ void lds128(uint32_t addr, uint32_t* r) {
    asm volatile("ld.shared.v4.b32 {%0,%1,%2,%3}, [%4];"
                 : "=r"(r[0]), "=r"(r[1]), "=r"(r[2]), "=r"(r[3]) : "r"(addr));
}
__device__ __forceinline__ void ldsm_x4(uint32_t addr, uint32_t* r) {
    asm volatile("ldmatrix.sync.aligned.m8n8.x4.shared.b16 {%0,%1,%2,%3}, [%4];"
                 : "=r"(r[0]), "=r"(r[1]), "=r"(r[2]), "=r"(r[3]) : "r"(addr));
}
__device__ __forceinline__ void mma_f16(float* c, const uint32_t* a,
                                        uint32_t b0, uint32_t b1) {
    asm volatile(
        "mma.sync.aligned.m16n8k16.row.col.f32.f16.f16.f32 "
        "{%0,%1,%2,%3}, {%4,%5,%6,%7}, {%8,%9}, {%0,%1,%2,%3};"
        : "+f"(c[0]), "+f"(c[1]), "+f"(c[2]), "+f"(c[3])
        : "r"(a[0]), "r"(a[1]), "r"(a[2]), "r"(a[3]), "r"(b0), "r"(b1));
}

// ------------------------------------------------------- prepass (one batch)
// grid = 128 CTAs (one 128-point tile each), block = 512.
__global__ __launch_bounds__(512, 1) void prepass(
    const float* __restrict__ x, const float* __restrict__ pos,
    const float* __restrict__ ws, const float* __restrict__ we, int bb)
{
    extern __shared__ __align__(16) char sm[];
    const uint32_t smb = smem_u32(sm);
    const int tid = threadIdx.x, wid = tid >> 5, lane = tid & 31;
    const int tp0 = bb * Nn + (int)blockIdx.x * 128;   // global point base

    // --- stage W2^T fp32->fp16 transposed (half2-packed writes) ---
    for (int i = tid; i < 64 * 256; i += 512) {
        int k2 = i >> 8, n = i & 255, k = k2 * 2;
        float va = (n < 128) ? ws[k * 128 + n] : we[k * 128 + (n - 128)];
        float vb = (n < 128) ? ws[(k + 1) * 128 + n] : we[(k + 1) * 128 + (n - 128)];
        sts32(smb + SM_B2 + n * RB + k2 * 4, cvt2h(va, vb));
    }
    for (int i = tid; i < 256 * 4; i += 512) {          // zero pad k=128..135
        int n = i >> 2, q = i & 3;
        sts32(smb + SM_B2 + n * RB + 256 + q * 4, 0u);
    }

    // --- aug rows for this tile ---
    if (tid < 128) {
        int p = tp0 + tid;
        float px = pos[(size_t)p * 3], py = pos[(size_t)p * 3 + 1],
              pz = pos[(size_t)p * 3 + 2];
        *(float4*)(g_aug + (size_t)p * 4) =
            make_float4(px, py, pz, px * px + py * py + pz * pz);
    }

    // --- x tile fp32 -> fp16 smem ---
    #pragma unroll
    for (int it = 0; it < 8; ++it) {
        int j = tid + it * 512;
        int row = j >> 5, c4 = j & 31;
        float4 f = *(const float4*)(x + (size_t)(tp0 + row) * 128 + c4 * 4);
        sts64(smb + SM_A2 + row * RB + c4 * 8, cvt2h(f.x, f.y), cvt2h(f.z, f.w));
    }
    __syncthreads();

    // --- GEMM: 16 warps, warp tile m32 x n64 ---
    const int g8 = lane >> 3, r8 = lane & 7;
    const uint32_t a_off = (uint32_t)(((g8 & 1) * 8 + r8) * RB + (g8 >> 1) * 16);
    const uint32_t b_off = (uint32_t)(((g8 >> 1) * 8 + r8) * RB + (g8 & 1) * 16);
    const int mg = wid >> 2, ng = wid & 3;

    float c[2][8][4];
    #pragma unroll
    for (int mt = 0; mt < 2; ++mt)
        #pragma unroll
        for (int nt = 0; nt < 8; ++nt)
            #pragma unroll
            for (int q = 0; q < 4; ++q) c[mt][nt][q] = 0.f;

    const uint32_t Ab = smb + SM_A2 + (uint32_t)(mg * 32) * RB + a_off;
    const uint32_t Bb = smb + SM_B2 + (uint32_t)(ng * 64) * RB + b_off;
    #pragma unroll
    for (int kt = 0; kt < 8; ++kt) {
        uint32_t af[2][4], bf[4][4];
        ldsm_x4(Ab + kt * 32, af[0]);
        ldsm_x4(Ab + 16 * RB + kt * 32, af[1]);
        #pragma unroll
        for (int nn = 0; nn < 4; ++nn)
            ldsm_x4(Bb + (uint32_t)(nn * 16) * RB + kt * 32, bf[nn]);
        #pragma unroll
        for (int mt = 0; mt < 2; ++mt)
            #pragma unroll
            for (int nn = 0; nn < 4; ++nn) {
                mma_f16(c[mt][nn * 2],     af[mt], bf[nn][0], bf[nn][1]);
                mma_f16(c[mt][nn * 2 + 1], af[mt], bf[nn][2], bf[nn][3]);
            }
    }

    // --- frags -> y stage -> coalesced global store ---
    #pragma unroll
    for (int mt = 0; mt < 2; ++mt)
        #pragma unroll
        for (int nt = 0; nt < 8; ++nt) {
            int row = mg * 32 + mt * 16 + (lane >> 2);
            int col = ng * 64 + nt * 8 + 2 * (lane & 3);
            uint32_t ad = smb + SM_Y + (uint32_t)row * (YSTR * 2) + col * 2;
            sts32(ad, cvt2h(c[mt][nt][0], c[mt][nt][1]));
            sts32(ad + 8 * (YSTR * 2), cvt2h(c[mt][nt][2], c[mt][nt][3]));
        }
    __syncthreads();

    char* yt = (char*)(g_y + (size_t)tp0 * 256);
    #pragma unroll
    for (int it = 0; it < 8; ++it) {
        int j = tid + it * 512;
        int row = j >> 5, c16 = j & 31;
        uint32_t u[4];
        lds128(smb + SM_Y + (uint32_t)row * (YSTR * 2) + c16 * 16, u);
        *(uint4*)(yt + (size_t)row * 512 + c16 * 16) =
            make_uint4(u[0], u[1], u[2], u[3]);
    }
}

// -------------------------------------------------------- gather (one batch)
__global__ __launch_bounds__(256) void gather(
    const int* __restrict__ idx, const float* __restrict__ we,
    float* __restrict__ out, int bb)
{
    __shared__ __align__(16) float wpos[512];    // We rows 128..131
    const int tid = threadIdx.x;
    wpos[tid] = we[128 * 128 + tid];
    wpos[256 + tid] = we[128 * 128 + 256 + tid];
    __syncthreads();

    const int warp = tid >> 5, lane = tid & 31;
    const int l16 = lane & 15, h = lane >> 4;
    const int p = bb * Nn + (int)blockIdx.x * 8 + warp;   // global point

    int my = 0;
    if (lane < 16) my = __ldg(idx + (size_t)p * 16 + lane);

    // ---- edge mean: half-warp per neighbor row, uint4 (8 halves) per lane ----
    const __half* yb = g_y + ((size_t)bb << 14) * 256;
    float a0 = 0.f, a1 = 0.f, a2 = 0.f, a3 = 0.f,
          a4 = 0.f, a5 = 0.f, a6 = 0.f, a7 = 0.f;
    #pragma unroll
    for (int k = 0; k < 8; ++k) {
        int jA = __shfl_sync(0xffffffffu, my, 2 * k);
        int jB = __shfl_sync(0xffffffffu, my, 2 * k + 1);
        int j = h ? jB : jA;
        uint4 v = *(const uint4*)(yb + (size_t)j * 256 + 128 + l16 * 8);
        float2 f0 = __half22float2(*(__half2*)&v.x);
        float2 f1 = __half22float2(*(__half2*)&v.y);
        float2 f2 = __half22float2(*(__half2*)&v.z);
        float2 f3 = __half22float2(*(__half2*)&v.w);
        a0 += f0.x; a1 += f0.y; a2 += f1.x; a3 += f1.y;
        a4 += f2.x; a5 += f2.y; a6 += f3.x; a7 += f3.y;
    }
    a0 += __shfl_xor_sync(0xffffffffu, a0, 16);
    a1 += __shfl_xor_sync(0xffffffffu, a1, 16);
    a2 += __shfl_xor_sync(0xffffffffu, a2, 16);
    a3 += __shfl_xor_sync(0xffffffffu, a3, 16);
    a4 += __shfl_xor_sync(0xffffffffu, a4, 16);
    a5 += __shfl_xor_sync(0xffffffffu, a5, 16);
    a6 += __shfl_xor_sync(0xffffffffu, a6, 16);
    a7 += __shfl_xor_sync(0xffffffffu, a7, 16);

    // ---- aug mean (fp32 exact) ----
    float m0 = 0.f, m1 = 0.f, m2 = 0.f, m3 = 0.f;
    if (lane < 16) {
        float4 av = *(const float4*)(g_aug + ((size_t)(bb << 14) + my) * 4);
        m0 = av.x; m1 = av.y; m2 = av.z; m3 = av.w;
    }
    #pragma unroll
    for (int o = 8; o >= 1; o >>= 1) {
        m0 += __shfl_xor_sync(0xffffffffu, m0, o);
        m1 += __shfl_xor_sync(0xffffffffu, m1, o);
        m2 += __shfl_xor_sync(0xffffffffu, m2, o);
        m3 += __shfl_xor_sync(0xffffffffu, m3, o);
    }
    const float inv = 1.0f / 16.0f;
    m0 = __shfl_sync(0xffffffffu, m0, 0) * inv;
    m1 = __shfl_sync(0xffffffffu, m1, 0) * inv;
    m2 = __shfl_sync(0xffffffffu, m2, 0) * inv;
    m3 = __shfl_sync(0xffffffffu, m3, 0) * inv;

    float4 as_ = *(const float4*)(g_aug + (size_t)p * 4);
    float r0 = as_.x - m0, r1 = as_.y - m1, r2 = as_.z - m2;
    float ds = as_.w - 2.f * (as_.x * m0 + as_.y * m1 + as_.z * m2) + m3;

    // ---- self y cols l16*8 .. +7 ----
    uint4 sv = *(const uint4*)(g_y + (size_t)p * 256 + l16 * 8);
    float2 s0 = __half22float2(*(__half2*)&sv.x);
    float2 s1 = __half22float2(*(__half2*)&sv.y);
    float2 s2 = __half22float2(*(__half2*)&sv.z);
    float2 s3 = __half22float2(*(__half2*)&sv.w);

    // ---- pos weights for these 8 cols ----
    float4 w0a = *(const float4*)(wpos +       l16 * 8);
    float4 w0b = *(const float4*)(wpos +       l16 * 8 + 4);
    float4 w1a = *(const float4*)(wpos + 128 + l16 * 8);
    float4 w1b = *(const float4*)(wpos + 128 + l16 * 8 + 4);
    float4 w2a = *(const float4*)(wpos + 256 + l16 * 8);
    float4 w2b = *(const float4*)(wpos + 256 + l16 * 8 + 4);
    float4 w3a = *(const float4*)(wpos + 384 + l16 * 8);
    float4 w3b = *(const float4*)(wpos + 384 + l16 * 8 + 4);

    float v0 = s0.x + a0 * inv + r0 * w0a.x + r1 * w1a.x + r2 * w2a.x + ds * w3a.x;
    float v1 = s0.y + a1 * inv + r0 * w0a.y + r1 * w1a.y + r2 * w2a.y + ds * w3a.y;
    float v2 = s1.x + a2 * inv + r0 * w0a.z + r1 * w1a.z + r2 * w2a.z + ds * w3a.z;
    float v3 = s1.y + a3 * inv + r0 * w0a.w + r1 * w1a.w + r2 * w2a.w + ds * w3a.w;
    float v4 = s2.x + a4 * inv + r0 * w0b.x + r1 * w1b.x + r2 * w2b.x + ds * w3b.x;
    float v5 = s2.y + a5 * inv + r0 * w0b.y + r1 * w1b.y + r2 * w2b.y + ds * w3b.y;
    float v6 = s3.x + a6 * inv + r0 * w0b.z + r1 * w1b.z + r2 * w2b.z + ds * w3b.z;
    float v7 = s3.y + a7 * inv + r0 * w0b.w + r1 * w1b.w + r2 * w2b.w + ds * w3b.w;

    float4 r;
    r.x = h ? (v4 > 0.f ? v4 : 0.2f * v4) : (v0 > 0.f ? v0 : 0.2f * v0);
    r.y = h ? (v5 > 0.f ? v5 : 0.2f * v5) : (v1 > 0.f ? v1 : 0.2f * v1);
    r.z = h ? (v6 > 0.f ? v6 : 0.2f * v6) : (v2 > 0.f ? v2 : 0.2f * v2);
    r.w = h ? (v7 > 0.f ? v7 : 0.2f * v7) : (v3 > 0.f ? v3 : 0.2f * v3);
    __stcs((float4*)(out + (size_t)p * 128 + l16 * 8 + h * 4), r);
}

}  // namespace

extern "C" void kernel_launch(void* const* d_in, const int* in_sizes, int n_in,
                              void* d_out, int out_size) {
    const float* x   = (const float*)d_in[0];   // [8,16384,128]
    const float* pos = (const float*)d_in[1];   // [8,16384,3]
    const int*   idx = (const int*)d_in[2];     // [8,16384,16]
    const float* ws  = (const float*)d_in[3];   // [128,128]
    const float* we  = (const float*)d_in[4];   // [132,128]
    float* out = (float*)d_out;

    cudaFuncSetAttribute(prepass, cudaFuncAttributeMaxDynamicSharedMemorySize, SM2_TOTAL);

    // fork/join pipeline: gather(b) on s1 waits only on prepass(b)
    cudaStream_t s1;
    cudaStreamCreateWithFlags(&s1, cudaStreamNonBlocking);
    cudaEvent_t ev[8], done;
    for (int b = 0; b < 8; ++b)
        cudaEventCreateWithFlags(&ev[b], cudaEventDisableTiming);
    cudaEventCreateWithFlags(&done, cudaEventDisableTiming);

    for (int b = 0; b < 8; ++b) {
        prepass<<<128, 512, SM2_TOTAL>>>(x, pos, ws, we, b);
        cudaEventRecord(ev[b], 0);
        cudaStreamWaitEvent(s1, ev[b], 0);
        gather<<<2048, 256, 0, s1>>>(idx, we, out, b);
    }
    cudaEventRecord(done, s1);
    cudaStreamWaitEvent(0, done, 0);
}

// round 9
// speedup vs baseline: 1.2468x; 1.2468x over previous
#include <cuda_runtime.h>
#include <cuda_fp16.h>
#include <cstdint>

// GeometricEdgeConv v6: single-stream, two launches.
//  prepass: persistent; y[131072][256] fp16 = x @ [Ws | We_feat] (HMMA),
//           weights converted to smem in-CTA once; aug[p]=(pos,|pos|^2).
//  gather:  out[p] = leaky( y_self[p] + mean_k y_edge[idx] + pos-GEMV )
// (Round-8 lesson: per-batch launch chopping + events cost far more than
//  the prepass/gather overlap gains. Keep launches big.)

namespace {

constexpr int Nn = 16384;

constexpr int KH = 136;                    // 128 k + 8 pad halves
constexpr int RB = KH * 2;                 // 272 B row (LDSM conflict-free)
constexpr int SM_B2 = 0;                   // W2^T fp16: 256 rows
constexpr int SM_A2 = 256 * RB;            // x tile fp16
constexpr int SM_Y  = SM_A2 + 128 * RB;    // y stage: 128 x 264 halves
constexpr int YSTR  = 264;
constexpr int SM2_TOTAL = SM_Y + 128 * YSTR * 2;   // 172032

__device__ __half g_y[(size_t)131072 * 256];       // 64 MB scratch
__device__ float  g_aug[(size_t)131072 * 4];       // 2 MB: pos + |pos|^2

__device__ __forceinline__ uint32_t smem_u32(const void* p) {
    uint32_t a;
    asm("{ .reg .u64 t; cvta.to.shared.u64 t, %1; cvt.u32.u64 %0, t; }" : "=r"(a) : "l"(p));
    return a;
}
__device__ __forceinline__ uint32_t cvt2h(float a, float b) {  // lo=a, hi=b
    uint32_t r;
    asm("cvt.rn.f16x2.f32 %0, %1, %2;" : "=r"(r) : "f"(b), "f"(a));
    return r;
}
__device__ __forceinline__ void sts32(uint32_t addr, uint32_t v) {
    asm volatile("st.shared.b32 [%0], %1;" :: "r"(addr), "r"(v) : "memory");
}
__device__ __forceinline__ void sts64(uint32_t addr, uint32_t a, uint32_t b) {
    asm volatile("st.shared.v2.b32 [%0], {%1,%2};" :: "r"(addr), "r"(a), "r"(b) : "memory");
}
__device__ __forceinline__ void lds128(uint32_t addr, uint32_t* r) {
    asm volatile("ld.shared.v4.b32 {%0,%1,%2,%3}, [%4];"
                 : "=r"(r[0]), "=r"(r[1]), "=r"(r[2]), "=r"(r[3]) : "r"(addr));
}
__device__ __forceinline__ void ldsm_x4(uint32_t addr, uint32_t* r) {
    asm volatile("ldmatrix.sync.aligned.m8n8.x4.shared.b16 {%0,%1,%2,%3}, [%4];"
                 : "=r"(r[0]), "=r"(r[1]), "=r"(r[2]), "=r"(r[3]) : "r"(addr));
}
__device__ __forceinline__ void mma_f16(float* c, const uint32_t* a,
                                        uint32_t b0, uint32_t b1) {
    asm volatile(
        "mma.sync.aligned.m16n8k16.row.col.f32.f16.f16.f32 "
        "{%0,%1,%2,%3}, {%4,%5,%6,%7}, {%8,%9}, {%0,%1,%2,%3};"
        : "+f"(c[0]), "+f"(c[1]), "+f"(c[2]), "+f"(c[3])
        : "r"(a[0]), "r"(a[1]), "r"(a[2]), "r"(a[3]), "r"(b0), "r"(b1));
}

// ----------------------------------------------------------------- prepass
__global__ __launch_bounds__(512, 1) void prepass(
    const float* __restrict__ x, const float* __restrict__ pos,
    const float* __restrict__ ws, const float* __restrict__ we)
{
    extern __shared__ __align__(16) char sm[];
    const uint32_t smb = smem_u32(sm);
    const int tid = threadIdx.x, wid = tid >> 5, lane = tid & 31;

    // --- stage W2^T fp32->fp16 transposed, once per CTA ---
    for (int i = tid; i < 64 * 256; i += 512) {
        int k2 = i >> 8, n = i & 255, k = k2 * 2;
        float va = (n < 128) ? ws[k * 128 + n] : we[k * 128 + (n - 128)];
        float vb = (n < 128) ? ws[(k + 1) * 128 + n] : we[(k + 1) * 128 + (n - 128)];
        sts32(smb + SM_B2 + n * RB + k2 * 4, cvt2h(va, vb));
    }
    for (int i = tid; i < 256 * 4; i += 512) {          // zero pad k=128..135
        int n = i >> 2, q = i & 3;
        sts32(smb + SM_B2 + n * RB + 256 + q * 4, 0u);
    }
    __syncthreads();

    const int g8 = lane >> 3, r8 = lane & 7;
    const uint32_t a_off = (uint32_t)(((g8 & 1) * 8 + r8) * RB + (g8 >> 1) * 16);
    const uint32_t b_off = (uint32_t)(((g8 >> 1) * 8 + r8) * RB + (g8 & 1) * 16);
    const int mg = wid >> 2, ng = wid & 3;

    for (int tile = blockIdx.x; tile < 1024; tile += gridDim.x) {
        const int tp0 = tile * 128;

        // aug rows for this tile
        if (tid < 128) {
            int p = tp0 + tid;
            float px = pos[(size_t)p * 3], py = pos[(size_t)p * 3 + 1],
                  pz = pos[(size_t)p * 3 + 2];
            *(float4*)(g_aug + (size_t)p * 4) =
                make_float4(px, py, pz, px * px + py * py + pz * pz);
        }

        // x tile fp32 -> fp16 smem
        #pragma unroll
        for (int it = 0; it < 8; ++it) {
            int j = tid + it * 512;
            int row = j >> 5, c4 = j & 31;
            float4 f = *(const float4*)(x + (size_t)(tp0 + row) * 128 + c4 * 4);
            sts64(smb + SM_A2 + row * RB + c4 * 8, cvt2h(f.x, f.y), cvt2h(f.z, f.w));
        }
        __syncthreads();

        float c[2][8][4];
        #pragma unroll
        for (int mt = 0; mt < 2; ++mt)
            #pragma unroll
            for (int nt = 0; nt < 8; ++nt)
                #pragma unroll
                for (int q = 0; q < 4; ++q) c[mt][nt][q] = 0.f;

        const uint32_t Ab = smb + SM_A2 + (uint32_t)(mg * 32) * RB + a_off;
        const uint32_t Bb = smb + SM_B2 + (uint32_t)(ng * 64) * RB + b_off;
        #pragma unroll
        for (int kt = 0; kt < 8; ++kt) {
            uint32_t af[2][4], bf[4][4];
            ldsm_x4(Ab + kt * 32, af[0]);
            ldsm_x4(Ab + 16 * RB + kt * 32, af[1]);
            #pragma unroll
            for (int nn = 0; nn < 4; ++nn)
                ldsm_x4(Bb + (uint32_t)(nn * 16) * RB + kt * 32, bf[nn]);
            #pragma unroll
            for (int mt = 0; mt < 2; ++mt)
                #pragma unroll
                for (int nn = 0; nn < 4; ++nn) {
                    mma_f16(c[mt][nn * 2],     af[mt], bf[nn][0], bf[nn][1]);
                    mma_f16(c[mt][nn * 2 + 1], af[mt], bf[nn][2], bf[nn][3]);
                }
        }

        // frags -> y stage (fp16) -> coalesced global store
        #pragma unroll
        for (int mt = 0; mt < 2; ++mt)
            #pragma unroll
            for (int nt = 0; nt < 8; ++nt) {
                int row = mg * 32 + mt * 16 + (lane >> 2);
                int col = ng * 64 + nt * 8 + 2 * (lane & 3);
                uint32_t ad = smb + SM_Y + (uint32_t)row * (YSTR * 2) + col * 2;
                sts32(ad, cvt2h(c[mt][nt][0], c[mt][nt][1]));
                sts32(ad + 8 * (YSTR * 2), cvt2h(c[mt][nt][2], c[mt][nt][3]));
            }
        __syncthreads();

        char* yt = (char*)(g_y + (size_t)tp0 * 256);
        #pragma unroll
        for (int it = 0; it < 8; ++it) {
            int j = tid + it * 512;
            int row = j >> 5, c16 = j & 31;
            uint32_t u[4];
            lds128(smb + SM_Y + (uint32_t)row * (YSTR * 2) + c16 * 16, u);
            *(uint4*)(yt + (size_t)row * 512 + c16 * 16) =
                make_uint4(u[0], u[1], u[2], u[3]);
        }
        __syncthreads();
    }
}

// ------------------------------------------------------------------ gather
__global__ __launch_bounds__(256) void gather(
    const int* __restrict__ idx, const float* __restrict__ we,
    float* __restrict__ out)
{
    __shared__ __align__(16) float wpos[512];    // We rows 128..131
    const int tid = threadIdx.x;
    wpos[tid] = we[128 * 128 + tid];
    wpos[256 + tid] = we[128 * 128 + 256 + tid];
    __syncthreads();

    const int warp = tid >> 5, lane = tid & 31;
    const int l16 = lane & 15, h = lane >> 4;
    const int p = (int)blockIdx.x * 8 + warp;          // global point
    const int b = p >> 14;
    const __half* yb = g_y + ((size_t)b << 14) * 256;
    const float* augb = g_aug + ((size_t)b << 14) * 4;

    int my = 0;
    if (lane < 16) my = __ldg(idx + (size_t)p * 16 + lane);

    // ---- edge mean: 2 neighbor rows per instr (half-warp each), uint4 ----
    float a0 = 0.f, a1 = 0.f, a2 = 0.f, a3 = 0.f,
          a4 = 0.f, a5 = 0.f, a6 = 0.f, a7 = 0.f;
    #pragma unroll
    for (int k = 0; k < 8; ++k) {
        int j = __shfl_sync(0xffffffffu, my, 2 * k + h);
        uint4 v = *(const uint4*)(yb + (size_t)j * 256 + 128 + l16 * 8);
        float2 f0 = __half22float2(*(__half2*)&v.x);
        float2 f1 = __half22float2(*(__half2*)&v.y);
        float2 f2 = __half22float2(*(__half2*)&v.z);
        float2 f3 = __half22float2(*(__half2*)&v.w);
        a0 += f0.x; a1 += f0.y; a2 += f1.x; a3 += f1.y;
        a4 += f2.x; a5 += f2.y; a6 += f3.x; a7 += f3.y;
    }
    a0 += __shfl_xor_sync(0xffffffffu, a0, 16);
    a1 += __shfl_xor_sync(0xffffffffu, a1, 16);
    a2 += __shfl_xor_sync(0xffffffffu, a2, 16);
    a3 += __shfl_xor_sync(0xffffffffu, a3, 16);
    a4 += __shfl_xor_sync(0xffffffffu, a4, 16);
    a5 += __shfl_xor_sync(0xffffffffu, a5, 16);
    a6 += __shfl_xor_sync(0xffffffffu, a6, 16);
    a7 += __shfl_xor_sync(0xffffffffu, a7, 16);

    // ---- aug mean (fp32 exact) ----
    float m0 = 0.f, m1 = 0.f, m2 = 0.f, m3 = 0.f;
    if (lane < 16) {
        float4 av = *(const float4*)(augb + (size_t)my * 4);
        m0 = av.x; m1 = av.y; m2 = av.z; m3 = av.w;
    }
    #pragma unroll
    for (int o = 8; o >= 1; o >>= 1) {
        m0 += __shfl_xor_sync(0xffffffffu, m0, o);
        m1 += __shfl_xor_sync(0xffffffffu, m1, o);
        m2 += __shfl_xor_sync(0xffffffffu, m2, o);
        m3 += __shfl_xor_sync(0xffffffffu, m3, o);
    }
    const float inv = 1.0f / 16.0f;
    m0 = __shfl_sync(0xffffffffu, m0, 0) * inv;
    m1 = __shfl_sync(0xffffffffu, m1, 0) * inv;
    m2 = __shfl_sync(0xffffffffu, m2, 0) * inv;
    m3 = __shfl_sync(0xffffffffu, m3, 0) * inv;

    float4 as_ = *(const float4*)(g_aug + (size_t)p * 4);
    float r0 = as_.x - m0, r1 = as_.y - m1, r2 = as_.z - m2;
    float ds = as_.w - 2.f * (as_.x * m0 + as_.y * m1 + as_.z * m2) + m3;

    // ---- self y cols l16*8 .. +7 ----
    uint4 sv = *(const uint4*)(g_y + (size_t)p * 256 + l16 * 8);
    float2 s0 = __half22float2(*(__half2*)&sv.x);
    float2 s1 = __half22float2(*(__half2*)&sv.y);
    float2 s2 = __half22float2(*(__half2*)&sv.z);
    float2 s3 = __half22float2(*(__half2*)&sv.w);

    float4 w0a = *(const float4*)(wpos +       l16 * 8);
    float4 w0b = *(const float4*)(wpos +       l16 * 8 + 4);
    float4 w1a = *(const float4*)(wpos + 128 + l16 * 8);
    float4 w1b = *(const float4*)(wpos + 128 + l16 * 8 + 4);
    float4 w2a = *(const float4*)(wpos + 256 + l16 * 8);
    float4 w2b = *(const float4*)(wpos + 256 + l16 * 8 + 4);
    float4 w3a = *(const float4*)(wpos + 384 + l16 * 8);
    float4 w3b = *(const float4*)(wpos + 384 + l16 * 8 + 4);

    float v0 = s0.x + a0 * inv + r0 * w0a.x + r1 * w1a.x + r2 * w2a.x + ds * w3a.x;
    float v1 = s0.y + a1 * inv + r0 * w0a.y + r1 * w1a.y + r2 * w2a.y + ds * w3a.y;
    float v2 = s1.x + a2 * inv + r0 * w0a.z + r1 * w1a.z + r2 * w2a.z + ds * w3a.z;
    float v3 = s1.y + a3 * inv + r0 * w0a.w + r1 * w1a.w + r2 * w2a.w + ds * w3a.w;
    float v4 = s2.x + a4 * inv + r0 * w0b.x + r1 * w1b.x + r2 * w2b.x + ds * w3b.x;
    float v5 = s2.y + a5 * inv + r0 * w0b.y + r1 * w1b.y + r2 * w2b.y + ds * w3b.y;
    float v6 = s3.x + a6 * inv + r0 * w0b.z + r1 * w1b.z + r2 * w2b.z + ds * w3b.z;
    float v7 = s3.y + a7 * inv + r0 * w0b.w + r1 * w1b.w + r2 * w2b.w + ds * w3b.w;

    float4 r;
    r.x = h ? (v4 > 0.f ? v4 : 0.2f * v4) : (v0 > 0.f ? v0 : 0.2f * v0);
    r.y = h ? (v5 > 0.f ? v5 : 0.2f * v5) : (v1 > 0.f ? v1 : 0.2f * v1);
    r.z = h ? (v6 > 0.f ? v6 : 0.2f * v6) : (v2 > 0.f ? v2 : 0.2f * v2);
    r.w = h ? (v7 > 0.f ? v7 : 0.2f * v7) : (v3 > 0.f ? v3 : 0.2f * v3);
    __stcs((float4*)(out + (size_t)p * 128 + l16 * 8 + h * 4), r);
}

}  // namespace

extern "C" void kernel_launch(void* const* d_in, const int* in_sizes, int n_in,
                              void* d_out, int out_size) {
    const float* x   = (const float*)d_in[0];   // [8,16384,128]
    const float* pos = (const float*)d_in[1];   // [8,16384,3]
    const int*   idx = (const int*)d_in[2];     // [8,16384,16]
    const float* ws  = (const float*)d_in[3];   // [128,128]
    const float* we  = (const float*)d_in[4];   // [132,128]
    float* out = (float*)d_out;

    cudaFuncSetAttribute(prepass, cudaFuncAttributeMaxDynamicSharedMemorySize, SM2_TOTAL);
    prepass<<<148, 512, SM2_TOTAL>>>(x, pos, ws, we);
    gather<<<16384, 256>>>(idx, we, out);
}

// round 10
// speedup vs baseline: 1.2909x; 1.0354x over previous
#include <cuda_runtime.h>
#include <cuda_fp16.h>
#include <cstdint>

// GeometricEdgeConv v7:
//  prepack: W2^T fp16 table (v4-proven) + aug[p]=(pos,|pos|^2) fill.
//  prepass: v4-exact persistent HMMA GEMM y = x @ [Ws | We_feat] (fp16 y).
//  gather:  2 warps per point (8 neighbors each, full-warp uint2 row loads),
//           partials combined in smem; both warps split the epilogue.

namespace {

constexpr int Nn = 16384;

constexpr int KH = 136;                    // 128 k + 8 pad halves
constexpr int RB = KH * 2;                 // 272 B row (LDSM conflict-free)
constexpr int SM_B2 = 0;
constexpr int SM_A2 = 256 * RB;
constexpr int SM_Y  = SM_A2 + 128 * RB;
constexpr int YSTR  = 264;
constexpr int SM2_TOTAL = SM_Y + 128 * YSTR * 2;   // 172032

__device__ __half g_wt2[256 * KH];
__device__ __half g_y[(size_t)131072 * 256];       // 64 MB scratch
__device__ float  g_aug[(size_t)131072 * 4];       // pos + |pos|^2

__device__ __forceinline__ uint32_t smem_u32(const void* p) {
    uint32_t a;
    asm("{ .reg .u64 t; cvta.to.shared.u64 t, %1; cvt.u32.u64 %0, t; }" : "=r"(a) : "l"(p));
    return a;
}
__device__ __forceinline__ uint32_t cvt2h(float a, float b) {  // lo=a, hi=b
    uint32_t r;
    asm("cvt.rn.f16x2.f32 %0, %1, %2;" : "=r"(r) : "f"(b), "f"(a));
    return r;
}
__device__ __forceinline__ void sts32(uint32_t addr, uint32_t v) {
    asm volatile("st.shared.b32 [%0], %1;" :: "r"(addr), "r"(v) : "memory");
}
__device__ __forceinline__ void sts64(uint32_t addr, uint32_t a, uint32_t b) {
    asm volatile("st.shared.v2.b32 [%0], {%1,%2};" :: "r"(addr), "r"(a), "r"(b) : "memory");
}
__device__ __forceinline__ void lds128(uint32_t addr, uint32_t* r) {
    asm volatile("ld.shared.v4.b32 {%0,%1,%2,%3}, [%4];"
                 : "=r"(r[0]), "=r"(r[1]), "=r"(r[2]), "=r"(r[3]) : "r"(addr));
}
__device__ __forceinline__ void ldsm_x4(uint32_t addr, uint32_t* r) {
    asm volatile("ldmatrix.sync.aligned.m8n8.x4.shared.b16 {%0,%1,%2,%3}, [%4];"
                 : "=r"(r[0]), "=r"(r[1]), "=r"(r[2]), "=r"(r[3]) : "r"(addr));
}
__device__ __forceinline__ void mma_f16(float* c, const uint32_t* a,
                                        uint32_t b0, uint32_t b1) {
    asm volatile(
        "mma.sync.aligned.m16n8k16.row.col.f32.f16.f16.f32 "
        "{%0,%1,%2,%3}, {%4,%5,%6,%7}, {%8,%9}, {%0,%1,%2,%3};"
        : "+f"(c[0]), "+f"(c[1]), "+f"(c[2]), "+f"(c[3])
        : "r"(a[0]), "r"(a[1]), "r"(a[2]), "r"(a[3]), "r"(b0), "r"(b1));
}

// ------------------------------------------------ prepack (+ aug fill)
__global__ void prepack(const float* __restrict__ ws, const float* __restrict__ we,
                        const float* __restrict__ pos) {
    if (blockIdx.x < 136) {
        int t = blockIdx.x * 256 + threadIdx.x;
        if (t >= 256 * KH) return;
        int n = t / KH, k = t % KH;
        float v = 0.f;
        if (k < 128) v = (n < 128) ? ws[k * 128 + n] : we[k * 128 + (n - 128)];
        g_wt2[t] = __float2half_rn(v);
    } else {
        int i = (blockIdx.x - 136) * 256 + threadIdx.x;   // point id
        if (i >= 131072) return;
        float px = pos[(size_t)i * 3], py = pos[(size_t)i * 3 + 1],
              pz = pos[(size_t)i * 3 + 2];
        *(float4*)(g_aug + (size_t)i * 4) =
            make_float4(px, py, pz, px * px + py * py + pz * pz);
    }
}

// ------------------------------------------------ prepass (v4-exact)
__global__ __launch_bounds__(512, 1) void prepass(const float* __restrict__ x) {
    extern __shared__ __align__(16) char sm[];
    const uint32_t smb = smem_u32(sm);
    const int tid = threadIdx.x, wid = tid >> 5, lane = tid & 31;

    {
        const int4* s = (const int4*)g_wt2;
        int4* d = (int4*)(sm + SM_B2);
        for (int i = tid; i < 256 * RB / 16; i += 512) d[i] = s[i];
    }
    __syncthreads();

    const int g8 = lane >> 3, r8 = lane & 7;
    const uint32_t a_off = (uint32_t)(((g8 & 1) * 8 + r8) * RB + (g8 >> 1) * 16);
    const uint32_t b_off = (uint32_t)(((g8 >> 1) * 8 + r8) * RB + (g8 & 1) * 16);
    const int mg = wid >> 2, ng = wid & 3;

    for (int tile = blockIdx.x; tile < 1024; tile += gridDim.x) {
        const int tp0 = tile * 128;

        #pragma unroll
        for (int it = 0; it < 8; ++it) {
            int j = tid + it * 512;
            int row = j >> 5, c4 = j & 31;
            float4 f = *(const float4*)(x + (size_t)(tp0 + row) * 128 + c4 * 4);
            sts64(smb + SM_A2 + row * RB + c4 * 8, cvt2h(f.x, f.y), cvt2h(f.z, f.w));
        }
        __syncthreads();

        float c[2][8][4];
        #pragma unroll
        for (int mt = 0; mt < 2; ++mt)
            #pragma unroll
            for (int nt = 0; nt < 8; ++nt)
                #pragma unroll
                for (int q = 0; q < 4; ++q) c[mt][nt][q] = 0.f;

        const uint32_t Ab = smb + SM_A2 + (uint32_t)(mg * 32) * RB + a_off;
        const uint32_t Bb = smb + SM_B2 + (uint32_t)(ng * 64) * RB + b_off;
        #pragma unroll
        for (int kt = 0; kt < 8; ++kt) {
            uint32_t af[2][4], bf[4][4];
            ldsm_x4(Ab + kt * 32, af[0]);
            ldsm_x4(Ab + 16 * RB + kt * 32, af[1]);
            #pragma unroll
            for (int nn = 0; nn < 4; ++nn)
                ldsm_x4(Bb + (uint32_t)(nn * 16) * RB + kt * 32, bf[nn]);
            #pragma unroll
            for (int mt = 0; mt < 2; ++mt)
                #pragma unroll
                for (int nn = 0; nn < 4; ++nn) {
                    mma_f16(c[mt][nn * 2],     af[mt], bf[nn][0], bf[nn][1]);
                    mma_f16(c[mt][nn * 2 + 1], af[mt], bf[nn][2], bf[nn][3]);
                }
        }

        #pragma unroll
        for (int mt = 0; mt < 2; ++mt)
            #pragma unroll
            for (int nt = 0; nt < 8; ++nt) {
                int row = mg * 32 + mt * 16 + (lane >> 2);
                int col = ng * 64 + nt * 8 + 2 * (lane & 3);
                uint32_t ad = smb + SM_Y + (uint32_t)row * (YSTR * 2) + col * 2;
                sts32(ad, cvt2h(c[mt][nt][0], c[mt][nt][1]));
                sts32(ad + 8 * (YSTR * 2), cvt2h(c[mt][nt][2], c[mt][nt][3]));
            }
        __syncthreads();

        char* yt = (char*)(g_y + (size_t)tp0 * 256);
        #pragma unroll
        for (int it = 0; it < 8; ++it) {
            int j = tid + it * 512;
            int row = j >> 5, c16 = j & 31;
            uint32_t u[4];
            lds128(smb + SM_Y + (uint32_t)row * (YSTR * 2) + c16 * 16, u);
            *(uint4*)(yt + (size_t)row * 512 + c16 * 16) =
                make_uint4(u[0], u[1], u[2], u[3]);
        }
        __syncthreads();
    }
}

// ------------------------------------------------ gather: 2 warps / point
__global__ __launch_bounds__(256) void gather(
    const int* __restrict__ idx, const float* __restrict__ we,
    float* __restrict__ out)
{
    __shared__ __align__(16) float part[4][2][128];  // edge partial sums
    __shared__ __align__(16) float4 paug[4][2];      // aug partial sums
    __shared__ __align__(16) float wpos[512];        // We rows 128..131

    const int tid = threadIdx.x;
    wpos[tid] = we[128 * 128 + tid];
    wpos[256 + tid] = we[128 * 128 + 256 + tid];

    const int warp = tid >> 5, lane = tid & 31;
    const int pt = warp >> 1, w = warp & 1;
    const int p = (int)blockIdx.x * 4 + pt;            // global point
    const int b = p >> 14;
    const __half* yb = g_y + ((size_t)b << 14) * 256;
    const float* augb = g_aug + ((size_t)b << 14) * 4;

    int my = 0;
    if (lane < 8) my = __ldg(idx + (size_t)p * 16 + w * 8 + lane);

    // ---- 8 neighbor rows, full-warp uint2 (4 halves per lane) ----
    float a0 = 0.f, a1 = 0.f, a2 = 0.f, a3 = 0.f;
    #pragma unroll
    for (int k = 0; k < 8; ++k) {
        int j = __shfl_sync(0xffffffffu, my, k);
        uint2 v = *(const uint2*)(yb + (size_t)j * 256 + 128 + lane * 4);
        float2 f0 = __half22float2(*(__half2*)&v.x);
        float2 f1 = __half22float2(*(__half2*)&v.y);
        a0 += f0.x; a1 += f0.y; a2 += f1.x; a3 += f1.y;
    }
    *(float4*)&part[pt][w][4 * lane] = make_float4(a0, a1, a2, a3);

    // ---- aug partial over this warp's 8 neighbors ----
    float m0 = 0.f, m1 = 0.f, m2 = 0.f, m3 = 0.f;
    if (lane < 8) {
        float4 av = *(const float4*)(augb + (size_t)my * 4);
        m0 = av.x; m1 = av.y; m2 = av.z; m3 = av.w;
    }
    #pragma unroll
    for (int o = 4; o >= 1; o >>= 1) {
        m0 += __shfl_xor_sync(0xffffffffu, m0, o);
        m1 += __shfl_xor_sync(0xffffffffu, m1, o);
        m2 += __shfl_xor_sync(0xffffffffu, m2, o);
        m3 += __shfl_xor_sync(0xffffffffu, m3, o);
    }
    if (lane == 0) paug[pt][w] = make_float4(m0, m1, m2, m3);
    __syncthreads();

    // ---- epilogue: warp w handles cols c0 = 64w + 2*lane (2 cols) ----
    const int c0 = 64 * w + 2 * lane;
    const float inv = 1.0f / 16.0f;

    float2 e0 = *(const float2*)&part[pt][0][c0];
    float2 e1 = *(const float2*)&part[pt][1][c0];
    float sum0 = (e0.x + e1.x) * inv;
    float sum1 = (e0.y + e1.y) * inv;

    float4 pa = paug[pt][0], pb2 = paug[pt][1];
    float mm0 = (pa.x + pb2.x) * inv, mm1 = (pa.y + pb2.y) * inv;
    float mm2 = (pa.z + pb2.z) * inv, mm3 = (pa.w + pb2.w) * inv;

    float4 as_ = *(const float4*)(g_aug + (size_t)p * 4);
    float r0 = as_.x - mm0, r1 = as_.y - mm1, r2 = as_.z - mm2;
    float ds = as_.w - 2.f * (as_.x * mm0 + as_.y * mm1 + as_.z * mm2) + mm3;

    uint32_t sv = *(const uint32_t*)(g_y + (size_t)p * 256 + c0);
    float2 s = __half22float2(*(__half2*)&sv);

    float2 w0 = *(const float2*)&wpos[c0];
    float2 w1 = *(const float2*)&wpos[128 + c0];
    float2 w2 = *(const float2*)&wpos[256 + c0];
    float2 w3 = *(const float2*)&wpos[384 + c0];

    float v0 = s.x + sum0 + r0 * w0.x + r1 * w1.x + r2 * w2.x + ds * w3.x;
    float v1 = s.y + sum1 + r0 * w0.y + r1 * w1.y + r2 * w2.y + ds * w3.y;

    float2 r;
    r.x = v0 > 0.f ? v0 : 0.2f * v0;
    r.y = v1 > 0.f ? v1 : 0.2f * v1;
    __stcs((float2*)(out + (size_t)p * 128 + c0), r);
}

}  // namespace

extern "C" void kernel_launch(void* const* d_in, const int* in_sizes, int n_in,
                              void* d_out, int out_size) {
    const float* x   = (const float*)d_in[0];   // [8,16384,128]
    const float* pos = (const float*)d_in[1];   // [8,16384,3]
    const int*   idx = (const int*)d_in[2];     // [8,16384,16]
    const float* ws  = (const float*)d_in[3];   // [128,128]
    const float* we  = (const float*)d_in[4];   // [132,128]
    float* out = (float*)d_out;

    cudaFuncSetAttribute(prepass, cudaFuncAttributeMaxDynamicSharedMemorySize, SM2_TOTAL);
    prepack<<<136 + 512, 256>>>(ws, we, pos);
    prepass<<<148, 512, SM2_TOTAL>>>(x);
    gather<<<32768, 256>>>(idx, we, out);
}

// round 11
// speedup vs baseline: 1.5789x; 1.2231x over previous
#include <cuda_runtime.h>
#include <cuda_fp16.h>
#include <cstdint>

// GeometricEdgeConv v8:
//  prepack: W2^T fp16 table + aug[p]=(pos,|pos|^2)   (proven, 5us)
//  prepass: persistent HMMA y = x @ [Ws | We_feat]   (v4-exact, ~28us)
//  gather:  1 warp = 2 adjacent points. Full-warp uint2 edge-row loads
//           (proven fastest primitive), A/B interleaved for MLP; both
//           points' idx in one coalesced load; aug means via one scattered
//           float4 + half-warp reductions. No smem combine, no extra sync.

namespace {

constexpr int Nn = 16384;

constexpr int KH = 136;
constexpr int RB = KH * 2;                 // 272 B row (LDSM conflict-free)
constexpr int SM_B2 = 0;
constexpr int SM_A2 = 256 * RB;
constexpr int SM_Y  = SM_A2 + 128 * RB;
constexpr int YSTR  = 264;
constexpr int SM2_TOTAL = SM_Y + 128 * YSTR * 2;   // 172032

__device__ __half g_wt2[256 * KH];
__device__ __half g_y[(size_t)131072 * 256];       // 64 MB scratch
__device__ float  g_aug[(size_t)131072 * 4];       // pos + |pos|^2

__device__ __forceinline__ uint32_t smem_u32(const void* p) {
    uint32_t a;
    asm("{ .reg .u64 t; cvta.to.shared.u64 t, %1; cvt.u32.u64 %0, t; }" : "=r"(a) : "l"(p));
    return a;
}
__device__ __forceinline__ uint32_t cvt2h(float a, float b) {  // lo=a, hi=b
    uint32_t r;
    asm("cvt.rn.f16x2.f32 %0, %1, %2;" : "=r"(r) : "f"(b), "f"(a));
    return r;
}
__device__ __forceinline__ void sts32(uint32_t addr, uint32_t v) {
    asm volatile("st.shared.b32 [%0], %1;" :: "r"(addr), "r"(v) : "memory");
}
__device__ __forceinline__ void sts64(uint32_t addr, uint32_t a, uint32_t b) {
    asm volatile("st.shared.v2.b32 [%0], {%1,%2};" :: "r"(addr), "r"(a), "r"(b) : "memory");
}
__device__ __forceinline__ void lds128(uint32_t addr, uint32_t* r) {
    asm volatile("ld.shared.v4.b32 {%0,%1,%2,%3}, [%4];"
                 : "=r"(r[0]), "=r"(r[1]), "=r"(r[2]), "=r"(r[3]) : "r"(addr));
}
__device__ __forceinline__ void ldsm_x4(uint32_t addr, uint32_t* r) {
    asm volatile("ldmatrix.sync.aligned.m8n8.x4.shared.b16 {%0,%1,%2,%3}, [%4];"
                 : "=r"(r[0]), "=r"(r[1]), "=r"(r[2]), "=r"(r[3]) : "r"(addr));
}
__device__ __forceinline__ void mma_f16(float* c, const uint32_t* a,
                                        uint32_t b0, uint32_t b1) {
    asm volatile(
        "mma.sync.aligned.m16n8k16.row.col.f32.f16.f16.f32 "
        "{%0,%1,%2,%3}, {%4,%5,%6,%7}, {%8,%9}, {%0,%1,%2,%3};"
        : "+f"(c[0]), "+f"(c[1]), "+f"(c[2]), "+f"(c[3])
        : "r"(a[0]), "r"(a[1]), "r"(a[2]), "r"(a[3]), "r"(b0), "r"(b1));
}

// ------------------------------------------------ prepack (+ aug fill)
__global__ void prepack(const float* __restrict__ ws, const float* __restrict__ we,
                        const float* __restrict__ pos) {
    if (blockIdx.x < 136) {
        int t = blockIdx.x * 256 + threadIdx.x;
        if (t >= 256 * KH) return;
        int n = t / KH, k = t % KH;
        float v = 0.f;
        if (k < 128) v = (n < 128) ? ws[k * 128 + n] : we[k * 128 + (n - 128)];
        g_wt2[t] = __float2half_rn(v);
    } else {
        int i = (blockIdx.x - 136) * 256 + threadIdx.x;
        if (i >= 131072) return;
        float px = pos[(size_t)i * 3], py = pos[(size_t)i * 3 + 1],
              pz = pos[(size_t)i * 3 + 2];
        *(float4*)(g_aug + (size_t)i * 4) =
            make_float4(px, py, pz, px * px + py * py + pz * pz);
    }
}

// ------------------------------------------------ prepass (v4-exact)
__global__ __launch_bounds__(512, 1) void prepass(const float* __restrict__ x) {
    extern __shared__ __align__(16) char sm[];
    const uint32_t smb = smem_u32(sm);
    const int tid = threadIdx.x, wid = tid >> 5, lane = tid & 31;

    {
        const int4* s = (const int4*)g_wt2;
        int4* d = (int4*)(sm + SM_B2);
        for (int i = tid; i < 256 * RB / 16; i += 512) d[i] = s[i];
    }
    __syncthreads();

    const int g8 = lane >> 3, r8 = lane & 7;
    const uint32_t a_off = (uint32_t)(((g8 & 1) * 8 + r8) * RB + (g8 >> 1) * 16);
    const uint32_t b_off = (uint32_t)(((g8 >> 1) * 8 + r8) * RB + (g8 & 1) * 16);
    const int mg = wid >> 2, ng = wid & 3;

    for (int tile = blockIdx.x; tile < 1024; tile += gridDim.x) {
        const int tp0 = tile * 128;

        #pragma unroll
        for (int it = 0; it < 8; ++it) {
            int j = tid + it * 512;
            int row = j >> 5, c4 = j & 31;
            float4 f = *(const float4*)(x + (size_t)(tp0 + row) * 128 + c4 * 4);
            sts64(smb + SM_A2 + row * RB + c4 * 8, cvt2h(f.x, f.y), cvt2h(f.z, f.w));
        }
        __syncthreads();

        float c[2][8][4];
        #pragma unroll
        for (int mt = 0; mt < 2; ++mt)
            #pragma unroll
            for (int nt = 0; nt < 8; ++nt)
                #pragma unroll
                for (int q = 0; q < 4; ++q) c[mt][nt][q] = 0.f;

        const uint32_t Ab = smb + SM_A2 + (uint32_t)(mg * 32) * RB + a_off;
        const uint32_t Bb = smb + SM_B2 + (uint32_t)(ng * 64) * RB + b_off;
        #pragma unroll
        for (int kt = 0; kt < 8; ++kt) {
            uint32_t af[2][4], bf[4][4];
            ldsm_x4(Ab + kt * 32, af[0]);
            ldsm_x4(Ab + 16 * RB + kt * 32, af[1]);
            #pragma unroll
            for (int nn = 0; nn < 4; ++nn)
                ldsm_x4(Bb + (uint32_t)(nn * 16) * RB + kt * 32, bf[nn]);
            #pragma unroll
            for (int mt = 0; mt < 2; ++mt)
                #pragma unroll
                for (int nn = 0; nn < 4; ++nn) {
                    mma_f16(c[mt][nn * 2],     af[mt], bf[nn][0], bf[nn][1]);
                    mma_f16(c[mt][nn * 2 + 1], af[mt], bf[nn][2], bf[nn][3]);
                }
        }

        #pragma unroll
        for (int mt = 0; mt < 2; ++mt)
            #pragma unroll
            for (int nt = 0; nt < 8; ++nt) {
                int row = mg * 32 + mt * 16 + (lane >> 2);
                int col = ng * 64 + nt * 8 + 2 * (lane & 3);
                uint32_t ad = smb + SM_Y + (uint32_t)row * (YSTR * 2) + col * 2;
                sts32(ad, cvt2h(c[mt][nt][0], c[mt][nt][1]));
                sts32(ad + 8 * (YSTR * 2), cvt2h(c[mt][nt][2], c[mt][nt][3]));
            }
        __syncthreads();

        char* yt = (char*)(g_y + (size_t)tp0 * 256);
        #pragma unroll
        for (int it = 0; it < 8; ++it) {
            int j = tid + it * 512;
            int row = j >> 5, c16 = j & 31;
            uint32_t u[4];
            lds128(smb + SM_Y + (uint32_t)row * (YSTR * 2) + c16 * 16, u);
            *(uint4*)(yt + (size_t)row * 512 + c16 * 16) =
                make_uint4(u[0], u[1], u[2], u[3]);
        }
        __syncthreads();
    }
}

// ------------------------------------------------ gather: 1 warp = 2 points
__global__ __launch_bounds__(256) void gather(
    const int* __restrict__ idx, const float* __restrict__ we,
    float* __restrict__ out)
{
    __shared__ __align__(16) float wpos[512];    // We rows 128..131
    const int tid = threadIdx.x;
    wpos[tid] = we[128 * 128 + tid];
    wpos[256 + tid] = we[128 * 128 + 256 + tid];
    __syncthreads();

    const int warp = tid >> 5, lane = tid & 31;
    const int pA = (int)blockIdx.x * 16 + warp * 2;    // 2 adjacent points
    const int pB = pA + 1;
    const int b = pA >> 14;                            // same batch for A,B
    const __half* yb = g_y + ((size_t)b << 14) * 256;
    const float* augb = g_aug + ((size_t)b << 14) * 4;
    const float inv = 1.0f / 16.0f;

    // both points' 16 indices: one coalesced 128B load
    int my = __ldg(idx + (size_t)pA * 16 + lane);      // lanes 0-15:A, 16-31:B

    // ---- edge means: A/B interleaved full-warp uint2 row loads ----
    float aA0 = 0.f, aA1 = 0.f, aA2 = 0.f, aA3 = 0.f;
    float aB0 = 0.f, aB1 = 0.f, aB2 = 0.f, aB3 = 0.f;
    #pragma unroll
    for (int k = 0; k < 16; ++k) {
        int jA = __shfl_sync(0xffffffffu, my, k);
        int jB = __shfl_sync(0xffffffffu, my, 16 + k);
        uint2 vA = *(const uint2*)(yb + (size_t)jA * 256 + 128 + lane * 4);
        uint2 vB = *(const uint2*)(yb + (size_t)jB * 256 + 128 + lane * 4);
        float2 fA0 = __half22float2(*(__half2*)&vA.x);
        float2 fA1 = __half22float2(*(__half2*)&vA.y);
        float2 fB0 = __half22float2(*(__half2*)&vB.x);
        float2 fB1 = __half22float2(*(__half2*)&vB.y);
        aA0 += fA0.x; aA1 += fA0.y; aA2 += fA1.x; aA3 += fA1.y;
        aB0 += fB0.x; aB1 += fB0.y; aB2 += fB1.x; aB3 += fB1.y;
    }

    // ---- aug means: one scattered float4, half-warp reductions ----
    float4 av = *(const float4*)(augb + (size_t)my * 4);
    float m0 = av.x, m1 = av.y, m2 = av.z, m3 = av.w;
    #pragma unroll
    for (int o = 8; o >= 1; o >>= 1) {
        m0 += __shfl_xor_sync(0xffffffffu, m0, o);
        m1 += __shfl_xor_sync(0xffffffffu, m1, o);
        m2 += __shfl_xor_sync(0xffffffffu, m2, o);
        m3 += __shfl_xor_sync(0xffffffffu, m3, o);
    }
    float mA0 = __shfl_sync(0xffffffffu, m0, 0) * inv;
    float mA1 = __shfl_sync(0xffffffffu, m1, 0) * inv;
    float mA2 = __shfl_sync(0xffffffffu, m2, 0) * inv;
    float mA3 = __shfl_sync(0xffffffffu, m3, 0) * inv;
    float mB0 = __shfl_sync(0xffffffffu, m0, 16) * inv;
    float mB1 = __shfl_sync(0xffffffffu, m1, 16) * inv;
    float mB2 = __shfl_sync(0xffffffffu, m2, 16) * inv;
    float mB3 = __shfl_sync(0xffffffffu, m3, 16) * inv;

    float4 asA = *(const float4*)(g_aug + (size_t)pA * 4);   // broadcast
    float4 asB = *(const float4*)(g_aug + (size_t)pB * 4);
    float rA0 = asA.x - mA0, rA1 = asA.y - mA1, rA2 = asA.z - mA2;
    float dsA = asA.w - 2.f * (asA.x * mA0 + asA.y * mA1 + asA.z * mA2) + mA3;
    float rB0 = asB.x - mB0, rB1 = asB.y - mB1, rB2 = asB.z - mB2;
    float dsB = asB.w - 2.f * (asB.x * mB0 + asB.y * mB1 + asB.z * mB2) + mB3;

    // ---- self rows (contiguous 256B each) ----
    uint2 svA = *(const uint2*)(g_y + (size_t)pA * 256 + lane * 4);
    uint2 svB = *(const uint2*)(g_y + (size_t)pB * 256 + lane * 4);
    float2 sA0 = __half22float2(*(__half2*)&svA.x);
    float2 sA1 = __half22float2(*(__half2*)&svA.y);
    float2 sB0 = __half22float2(*(__half2*)&svB.x);
    float2 sB1 = __half22float2(*(__half2*)&svB.y);

    // ---- pos weights: this lane's 4 cols ----
    float4 w0 = *(const float4*)(wpos +       4 * lane);
    float4 w1 = *(const float4*)(wpos + 128 + 4 * lane);
    float4 w2 = *(const float4*)(wpos + 256 + 4 * lane);
    float4 w3 = *(const float4*)(wpos + 384 + 4 * lane);

    float v0 = sA0.x + aA0 * inv + rA0 * w0.x + rA1 * w1.x + rA2 * w2.x + dsA * w3.x;
    float v1 = sA0.y + aA1 * inv + rA0 * w0.y + rA1 * w1.y + rA2 * w2.y + dsA * w3.y;
    float v2 = sA1.x + aA2 * inv + rA0 * w0.z + rA1 * w1.z + rA2 * w2.z + dsA * w3.z;
    float v3 = sA1.y + aA3 * inv + rA0 * w0.w + rA1 * w1.w + rA2 * w2.w + dsA * w3.w;
    float4 rA;
    rA.x = v0 > 0.f ? v0 : 0.2f * v0;
    rA.y = v1 > 0.f ? v1 : 0.2f * v1;
    rA.z = v2 > 0.f ? v2 : 0.2f * v2;
    rA.w = v3 > 0.f ? v3 : 0.2f * v3;
    __stcs((float4*)(out + (size_t)pA * 128 + 4 * lane), rA);

    float u0 = sB0.x + aB0 * inv + rB0 * w0.x + rB1 * w1.x + rB2 * w2.x + dsB * w3.x;
    float u1 = sB0.y + aB1 * inv + rB0 * w0.y + rB1 * w1.y + rB2 * w2.y + dsB * w3.y;
    float u2 = sB1.x + aB2 * inv + rB0 * w0.z + rB1 * w1.z + rB2 * w2.z + dsB * w3.z;
    float u3 = sB1.y + aB3 * inv + rB0 * w0.w + rB1 * w1.w + rB2 * w2.w + dsB * w3.w;
    float4 rB;
    rB.x = u0 > 0.f ? u0 : 0.2f * u0;
    rB.y = u1 > 0.f ? u1 : 0.2f * u1;
    rB.z = u2 > 0.f ? u2 : 0.2f * u2;
    rB.w = u3 > 0.f ? u3 : 0.2f * u3;
    __stcs((float4*)(out + (size_t)pB * 128 + 4 * lane), rB);
}

}  // namespace

extern "C" void kernel_launch(void* const* d_in, const int* in_sizes, int n_in,
                              void* d_out, int out_size) {
    const float* x   = (const float*)d_in[0];   // [8,16384,128]
    const float* pos = (const float*)d_in[1];   // [8,16384,3]
    const int*   idx = (const int*)d_in[2];     // [8,16384,16]
    const float* ws  = (const float*)d_in[3];   // [128,128]
    const float* we  = (const float*)d_in[4];   // [132,128]
    float* out = (float*)d_out;

    cudaFuncSetAttribute(prepass, cudaFuncAttributeMaxDynamicSharedMemorySize, SM2_TOTAL);
    prepack<<<136 + 512, 256>>>(ws, we, pos);
    prepass<<<148, 512, SM2_TOTAL>>>(x);
    gather<<<8192, 256>>>(idx, we, out);    // 2 points per warp
}

// round 12
// speedup vs baseline: 1.6308x; 1.0328x over previous
#include <cuda_runtime.h>
#include <cuda_fp16.h>
#include <cstdint>

// GeometricEdgeConv v9:
//  prepack: W2^T fp16 table + aug[p]=(pos,|pos|^2)   (proven)
//  prepass: persistent HMMA y = x @ [Ws | We_feat]   (v4-exact)
//  gather:  1 warp = 2 points; edge rows loaded into register ARRAYS
//           (explicit load-all-then-reduce) to force 32-deep MLP --
//           round-11 ncu showed regs=38 was strangling load batching.

namespace {

constexpr int Nn = 16384;

constexpr int KH = 136;
constexpr int RB = KH * 2;                 // 272 B row (LDSM conflict-free)
constexpr int SM_B2 = 0;
constexpr int SM_A2 = 256 * RB;
constexpr int SM_Y  = SM_A2 + 128 * RB;
constexpr int YSTR  = 264;
constexpr int SM2_TOTAL = SM_Y + 128 * YSTR * 2;   // 172032

__device__ __half g_wt2[256 * KH];
__device__ __half g_y[(size_t)131072 * 256];       // 64 MB scratch
__device__ float  g_aug[(size_t)131072 * 4];       // pos + |pos|^2

__device__ __forceinline__ uint32_t smem_u32(const void* p) {
    uint32_t a;
    asm("{ .reg .u64 t; cvta.to.shared.u64 t, %1; cvt.u32.u64 %0, t; }" : "=r"(a) : "l"(p));
    return a;
}
__device__ __forceinline__ uint32_t cvt2h(float a, float b) {  // lo=a, hi=b
    uint32_t r;
    asm("cvt.rn.f16x2.f32 %0, %1, %2;" : "=r"(r) : "f"(b), "f"(a));
    return r;
}
__device__ __forceinline__ void sts32(uint32_t addr, uint32_t v) {
    asm volatile("st.shared.b32 [%0], %1;" :: "r"(addr), "r"(v) : "memory");
}
__device__ __forceinline__ void sts64(uint32_t addr, uint32_t a, uint32_t b) {
    asm volatile("st.shared.v2.b32 [%0], {%1,%2};" :: "r"(addr), "r"(a), "r"(b) : "memory");
}
__device__ __forceinline__ void lds128(uint32_t addr, uint32_t* r) {
    asm volatile("ld.shared.v4.b32 {%0,%1,%2,%3}, [%4];"
                 : "=r"(r[0]), "=r"(r[1]), "=r"(r[2]), "=r"(r[3]) : "r"(addr));
}
__device__ __forceinline__ void ldsm_x4(uint32_t addr, uint32_t* r) {
    asm volatile("ldmatrix.sync.aligned.m8n8.x4.shared.b16 {%0,%1,%2,%3}, [%4];"
                 : "=r"(r[0]), "=r"(r[1]), "=r"(r[2]), "=r"(r[3]) : "r"(addr));
}
__device__ __forceinline__ void mma_f16(float* c, const uint32_t* a,
                                        uint32_t b0, uint32_t b1) {
    asm volatile(
        "mma.sync.aligned.m16n8k16.row.col.f32.f16.f16.f32 "
        "{%0,%1,%2,%3}, {%4,%5,%6,%7}, {%8,%9}, {%0,%1,%2,%3};"
        : "+f"(c[0]), "+f"(c[1]), "+f"(c[2]), "+f"(c[3])
        : "r"(a[0]), "r"(a[1]), "r"(a[2]), "r"(a[3]), "r"(b0), "r"(b1));
}

// ------------------------------------------------ prepack (+ aug fill)
__global__ void prepack(const float* __restrict__ ws, const float* __restrict__ we,
                        const float* __restrict__ pos) {
    if (blockIdx.x < 136) {
        int t = blockIdx.x * 256 + threadIdx.x;
        if (t >= 256 * KH) return;
        int n = t / KH, k = t % KH;
        float v = 0.f;
        if (k < 128) v = (n < 128) ? ws[k * 128 + n] : we[k * 128 + (n - 128)];
        g_wt2[t] = __float2half_rn(v);
    } else {
        int i = (blockIdx.x - 136) * 256 + threadIdx.x;
        if (i >= 131072) return;
        float px = pos[(size_t)i * 3], py = pos[(size_t)i * 3 + 1],
              pz = pos[(size_t)i * 3 + 2];
        *(float4*)(g_aug + (size_t)i * 4) =
            make_float4(px, py, pz, px * px + py * py + pz * pz);
    }
}

// ------------------------------------------------ prepass (v4-exact)
__global__ __launch_bounds__(512, 1) void prepass(const float* __restrict__ x) {
    extern __shared__ __align__(16) char sm[];
    const uint32_t smb = smem_u32(sm);
    const int tid = threadIdx.x, wid = tid >> 5, lane = tid & 31;

    {
        const int4* s = (const int4*)g_wt2;
        int4* d = (int4*)(sm + SM_B2);
        for (int i = tid; i < 256 * RB / 16; i += 512) d[i] = s[i];
    }
    __syncthreads();

    const int g8 = lane >> 3, r8 = lane & 7;
    const uint32_t a_off = (uint32_t)(((g8 & 1) * 8 + r8) * RB + (g8 >> 1) * 16);
    const uint32_t b_off = (uint32_t)(((g8 >> 1) * 8 + r8) * RB + (g8 & 1) * 16);
    const int mg = wid >> 2, ng = wid & 3;

    for (int tile = blockIdx.x; tile < 1024; tile += gridDim.x) {
        const int tp0 = tile * 128;

        #pragma unroll
        for (int it = 0; it < 8; ++it) {
            int j = tid + it * 512;
            int row = j >> 5, c4 = j & 31;
            float4 f = *(const float4*)(x + (size_t)(tp0 + row) * 128 + c4 * 4);
            sts64(smb + SM_A2 + row * RB + c4 * 8, cvt2h(f.x, f.y), cvt2h(f.z, f.w));
        }
        __syncthreads();

        float c[2][8][4];
        #pragma unroll
        for (int mt = 0; mt < 2; ++mt)
            #pragma unroll
            for (int nt = 0; nt < 8; ++nt)
                #pragma unroll
                for (int q = 0; q < 4; ++q) c[mt][nt][q] = 0.f;

        const uint32_t Ab = smb + SM_A2 + (uint32_t)(mg * 32) * RB + a_off;
        const uint32_t Bb = smb + SM_B2 + (uint32_t)(ng * 64) * RB + b_off;
        #pragma unroll
        for (int kt = 0; kt < 8; ++kt) {
            uint32_t af[2][4], bf[4][4];
            ldsm_x4(Ab + kt * 32, af[0]);
            ldsm_x4(Ab + 16 * RB + kt * 32, af[1]);
            #pragma unroll
            for (int nn = 0; nn < 4; ++nn)
                ldsm_x4(Bb + (uint32_t)(nn * 16) * RB + kt * 32, bf[nn]);
            #pragma unroll
            for (int mt = 0; mt < 2; ++mt)
                #pragma unroll
                for (int nn = 0; nn < 4; ++nn) {
                    mma_f16(c[mt][nn * 2],     af[mt], bf[nn][0], bf[nn][1]);
                    mma_f16(c[mt][nn * 2 + 1], af[mt], bf[nn][2], bf[nn][3]);
                }
        }

        #pragma unroll
        for (int mt = 0; mt < 2; ++mt)
            #pragma unroll
            for (int nt = 0; nt < 8; ++nt) {
                int row = mg * 32 + mt * 16 + (lane >> 2);
                int col = ng * 64 + nt * 8 + 2 * (lane & 3);
                uint32_t ad = smb + SM_Y + (uint32_t)row * (YSTR * 2) + col * 2;
                sts32(ad, cvt2h(c[mt][nt][0], c[mt][nt][1]));
                sts32(ad + 8 * (YSTR * 2), cvt2h(c[mt][nt][2], c[mt][nt][3]));
            }
        __syncthreads();

        char* yt = (char*)(g_y + (size_t)tp0 * 256);
        #pragma unroll
        for (int it = 0; it < 8; ++it) {
            int j = tid + it * 512;
            int row = j >> 5, c16 = j & 31;
            uint32_t u[4];
            lds128(smb + SM_Y + (uint32_t)row * (YSTR * 2) + c16 * 16, u);
            *(uint4*)(yt + (size_t)row * 512 + c16 * 16) =
                make_uint4(u[0], u[1], u[2], u[3]);
        }
        __syncthreads();
    }
}

// -------------------------------- gather: 1 warp = 2 points, batched loads
__global__ __launch_bounds__(256) void gather(
    const int* __restrict__ idx, const float* __restrict__ we,
    float* __restrict__ out)
{
    __shared__ __align__(16) float wpos[512];    // We rows 128..131
    const int tid = threadIdx.x;
    wpos[tid] = we[128 * 128 + tid];
    wpos[256 + tid] = we[128 * 128 + 256 + tid];
    __syncthreads();

    const int warp = tid >> 5, lane = tid & 31;
    const int pA = (int)blockIdx.x * 16 + warp * 2;
    const int pB = pA + 1;
    const int b = pA >> 14;
    const __half* yb = g_y + ((size_t)b << 14) * 256;
    const float* augb = g_aug + ((size_t)b << 14) * 4;
    const float inv = 1.0f / 16.0f;

    int my = __ldg(idx + (size_t)pA * 16 + lane);      // lanes 0-15:A, 16-31:B

    // ---- issue ALL 32 edge-row loads before any reduction (MLP=32) ----
    uint2 vA[16], vB[16];
    #pragma unroll
    for (int k = 0; k < 16; ++k) {
        int jA = __shfl_sync(0xffffffffu, my, k);
        vA[k] = *(const uint2*)(yb + (size_t)jA * 256 + 128 + lane * 4);
    }
    #pragma unroll
    for (int k = 0; k < 16; ++k) {
        int jB = __shfl_sync(0xffffffffu, my, 16 + k);
        vB[k] = *(const uint2*)(yb + (size_t)jB * 256 + 128 + lane * 4);
    }

    // aug gather overlaps the edge loads too
    float4 av = *(const float4*)(augb + (size_t)my * 4);
    uint2 svA = *(const uint2*)(g_y + (size_t)pA * 256 + lane * 4);
    uint2 svB = *(const uint2*)(g_y + (size_t)pB * 256 + lane * 4);

    // ---- reduce edge sums ----
    float aA0 = 0.f, aA1 = 0.f, aA2 = 0.f, aA3 = 0.f;
    float aB0 = 0.f, aB1 = 0.f, aB2 = 0.f, aB3 = 0.f;
    #pragma unroll
    for (int k = 0; k < 16; ++k) {
        float2 fA0 = __half22float2(*(__half2*)&vA[k].x);
        float2 fA1 = __half22float2(*(__half2*)&vA[k].y);
        float2 fB0 = __half22float2(*(__half2*)&vB[k].x);
        float2 fB1 = __half22float2(*(__half2*)&vB[k].y);
        aA0 += fA0.x; aA1 += fA0.y; aA2 += fA1.x; aA3 += fA1.y;
        aB0 += fB0.x; aB1 += fB0.y; aB2 += fB1.x; aB3 += fB1.y;
    }

    // ---- aug means (half-warp reductions) ----
    float m0 = av.x, m1 = av.y, m2 = av.z, m3 = av.w;
    #pragma unroll
    for (int o = 8; o >= 1; o >>= 1) {
        m0 += __shfl_xor_sync(0xffffffffu, m0, o);
        m1 += __shfl_xor_sync(0xffffffffu, m1, o);
        m2 += __shfl_xor_sync(0xffffffffu, m2, o);
        m3 += __shfl_xor_sync(0xffffffffu, m3, o);
    }
    float mA0 = __shfl_sync(0xffffffffu, m0, 0) * inv;
    float mA1 = __shfl_sync(0xffffffffu, m1, 0) * inv;
    float mA2 = __shfl_sync(0xffffffffu, m2, 0) * inv;
    float mA3 = __shfl_sync(0xffffffffu, m3, 0) * inv;
    float mB0 = __shfl_sync(0xffffffffu, m0, 16) * inv;
    float mB1 = __shfl_sync(0xffffffffu, m1, 16) * inv;
    float mB2 = __shfl_sync(0xffffffffu, m2, 16) * inv;
    float mB3 = __shfl_sync(0xffffffffu, m3, 16) * inv;

    float4 asA = *(const float4*)(g_aug + (size_t)pA * 4);
    float4 asB = *(const float4*)(g_aug + (size_t)pB * 4);
    float rA0 = asA.x - mA0, rA1 = asA.y - mA1, rA2 = asA.z - mA2;
    float dsA = asA.w - 2.f * (asA.x * mA0 + asA.y * mA1 + asA.z * mA2) + mA3;
    float rB0 = asB.x - mB0, rB1 = asB.y - mB1, rB2 = asB.z - mB2;
    float dsB = asB.w - 2.f * (asB.x * mB0 + asB.y * mB1 + asB.z * mB2) + mB3;

    float2 sA0 = __half22float2(*(__half2*)&svA.x);
    float2 sA1 = __half22float2(*(__half2*)&svA.y);
    float2 sB0 = __half22float2(*(__half2*)&svB.x);
    float2 sB1 = __half22float2(*(__half2*)&svB.y);

    float4 w0 = *(const float4*)(wpos +       4 * lane);
    float4 w1 = *(const float4*)(wpos + 128 + 4 * lane);
    float4 w2 = *(const float4*)(wpos + 256 + 4 * lane);
    float4 w3 = *(const float4*)(wpos + 384 + 4 * lane);

    float v0 = sA0.x + aA0 * inv + rA0 * w0.x + rA1 * w1.x + rA2 * w2.x + dsA * w3.x;
    float v1 = sA0.y + aA1 * inv + rA0 * w0.y + rA1 * w1.y + rA2 * w2.y + dsA * w3.y;
    float v2 = sA1.x + aA2 * inv + rA0 * w0.z + rA1 * w1.z + rA2 * w2.z + dsA * w3.z;
    float v3 = sA1.y + aA3 * inv + rA0 * w0.w + rA1 * w1.w + rA2 * w2.w + dsA * w3.w;
    float4 rA;
    rA.x = v0 > 0.f ? v0 : 0.2f * v0;
    rA.y = v1 > 0.f ? v1 : 0.2f * v1;
    rA.z = v2 > 0.f ? v2 : 0.2f * v2;
    rA.w = v3 > 0.f ? v3 : 0.2f * v3;
    __stcs((float4*)(out + (size_t)pA * 128 + 4 * lane), rA);

    float u0 = sB0.x + aB0 * inv + rB0 * w0.x + rB1 * w1.x + rB2 * w2.x + dsB * w3.x;
    float u1 = sB0.y + aB1 * inv + rB0 * w0.y + rB1 * w1.y + rB2 * w2.y + dsB * w3.y;
    float u2 = sB1.x + aB2 * inv + rB0 * w0.z + rB1 * w1.z + rB2 * w2.z + dsB * w3.z;
    float u3 = sB1.y + aB3 * inv + rB0 * w0.w + rB1 * w1.w + rB2 * w2.w + dsB * w3.w;
    float4 rB;
    rB.x = u0 > 0.f ? u0 : 0.2f * u0;
    rB.y = u1 > 0.f ? u1 : 0.2f * u1;
    rB.z = u2 > 0.f ? u2 : 0.2f * u2;
    rB.w = u3 > 0.f ? u3 : 0.2f * u3;
    __stcs((float4*)(out + (size_t)pB * 128 + 4 * lane), rB);
}

}  // namespace

extern "C" void kernel_launch(void* const* d_in, const int* in_sizes, int n_in,
                              void* d_out, int out_size) {
    const float* x   = (const float*)d_in[0];   // [8,16384,128]
    const float* pos = (const float*)d_in[1];   // [8,16384,3]
    const int*   idx = (const int*)d_in[2];     // [8,16384,16]
    const float* ws  = (const float*)d_in[3];   // [128,128]
    const float* we  = (const float*)d_in[4];   // [132,128]
    float* out = (float*)d_out;

    cudaFuncSetAttribute(prepass, cudaFuncAttributeMaxDynamicSharedMemorySize, SM2_TOTAL);
    prepack<<<136 + 512, 256>>>(ws, we, pos);
    prepass<<<148, 512, SM2_TOTAL>>>(x);
    gather<<<8192, 256>>>(idx, we, out);
}